// round 14
// baseline (speedup 1.0000x reference)
#include <cuda_runtime.h>
#include <math.h>
#include <stdint.h>

#define T_STEPS 12
#define HID     1024
#define B_SZ    2048
#define IMG     512
#define NCLS    51
#define MROWS   (T_STEPS * B_SZ)   /* 24576; row r = b*T + t */

#define SCALE_X 1.7320508075688772f  /* sqrt(3) */
#define QLEV    16256.0f             /* 127<<7 quant levels */

// ---------------- scratch (device globals; no allocations allowed) ----------
__device__ __align__(256) float g_U [(size_t)MROWS * 4096];
__device__ __align__(256) float g_h0[(size_t)MROWS * HID];
__device__ __align__(256) float g_h1[(size_t)MROWS * HID];
__device__ __align__(256) float g_hbar[(size_t)B_SZ * HID];
// int8 double-word quantized operands
__device__ __align__(256) int8_t g_qa_hi[(size_t)MROWS * HID];
__device__ __align__(256) int8_t g_qa_lo[(size_t)MROWS * HID];
__device__ __align__(256) int8_t g_qb_hi[(size_t)4096 * 1024];
__device__ __align__(256) int8_t g_qb_lo[(size_t)4096 * 1024];
__device__ __align__(256) float  g_sa[MROWS];
__device__ __align__(256) float  g_sb[4096];

// ======================= arch-neutral PTX helpers ===========================
__device__ __forceinline__ uint32_t smem_u32(const void* p) {
    uint32_t a;
    asm("{ .reg .u64 t; cvta.to.shared.u64 t, %1; cvt.u32.u64 %0, t; }"
        : "=r"(a) : "l"(p));
    return a;
}
__device__ __forceinline__ void cpa16(uint32_t dst, const void* src) {
    asm volatile("cp.async.cg.shared.global [%0], [%1], 16;"
                 :: "r"(dst), "l"(src) : "memory");
}
__device__ __forceinline__ void cpa_commit() {
    asm volatile("cp.async.commit_group;" ::: "memory");
}
__device__ __forceinline__ void cpa_wait1() {
    asm volatile("cp.async.wait_group 1;" ::: "memory");
}
__device__ __forceinline__ void ldsm4(uint32_t& r0, uint32_t& r1,
                                      uint32_t& r2, uint32_t& r3, uint32_t addr) {
    asm volatile("ldmatrix.sync.aligned.m8n8.x4.shared.b16 {%0,%1,%2,%3}, [%4];"
                 : "=r"(r0), "=r"(r1), "=r"(r2), "=r"(r3) : "r"(addr));
}
__device__ __forceinline__ void mma_s8(int* c, const uint32_t* a, const uint32_t* b) {
    asm volatile(
        "mma.sync.aligned.m16n8k32.row.col.s32.s8.s8.s32 "
        "{%0,%1,%2,%3}, {%4,%5,%6,%7}, {%8,%9}, {%0,%1,%2,%3};"
        : "+r"(c[0]), "+r"(c[1]), "+r"(c[2]), "+r"(c[3])
        : "r"(a[0]), "r"(a[1]), "r"(a[2]), "r"(a[3]), "r"(b[0]), "r"(b[1]));
}

// ======================= int8x3 tensor-core GEMM ============================
// C[M,N] (fp32) = sa_i*sb_j*(16384*sum(ah*bh) + 128*sum(ah*bl + al*bh)).
// A: [M,K] int8 hi/lo row-major; B: [N,K] int8 hi/lo (weights pre-transposed).
// CTA tile 128x128, K-chunk 128 (128B rows, XOR swizzle), 8 warps of 64x32,
// 3-stage cp.async pipeline, one barrier per chunk. grid=(N/128, M/128), 256 thr.
#define A_T   16384                 /* 128 rows x 128 B */
#define STG_B (4 * A_T)             /* Ah, Al, Bh, Bl = 64 KB */
#define SMEM_GEMM (3 * STG_B)       /* 192 KB */

__global__ void __launch_bounds__(256)
gemm_s8x3(const int8_t* __restrict__ Ah, const int8_t* __restrict__ Al,
          const int8_t* __restrict__ Bh, const int8_t* __restrict__ Bl,
          const float* __restrict__ sa, const float* __restrict__ sbv,
          float* __restrict__ C, int K, int Nld)
{
    extern __shared__ char smem[];
    const uint32_t sbase = smem_u32(smem);
    const int tid  = threadIdx.x;
    const int lane = tid & 31;
    const int wid  = tid >> 5;
    const int row0 = blockIdx.y * 128;
    const int col0 = blockIdx.x * 128;
    const int wm   = (wid >> 2) * 64;   // warp M offset (0/64)
    const int wn   = (wid & 3) * 32;    // warp N offset (0..96)

    const int NC = K >> 7;              // K/128 chunks (4 or 8)

    int acc1[4][4][4], acc2[4][4][4];
    #pragma unroll
    for (int i = 0; i < 4; ++i)
        #pragma unroll
        for (int j = 0; j < 4; ++j)
            #pragma unroll
            for (int q = 0; q < 4; ++q) { acc1[i][j][q] = 0; acc2[i][j][q] = 0; }

    // stage fill: 4 tiles x 1024 16B-chunks; 16 cp.async per thread
    auto fill = [&](int ck) {
        const int k0 = ck << 7;
        const uint32_t stg = sbase + (uint32_t)(ck % 3) * STG_B;
        #pragma unroll
        for (int i = 0; i < 4; ++i) {
            const int lin = tid + i * 256;     // 0..1023
            const int r   = lin >> 3;          // row 0..127
            const int c   = lin & 7;           // 16B chunk 0..7
            const uint32_t so = (uint32_t)(r * 128 + ((c ^ (r & 7)) << 4));
            const size_t ga = (size_t)(row0 + r) * K + k0 + c * 16;
            const size_t gb = (size_t)(col0 + r) * K + k0 + c * 16;
            cpa16(stg + 0 * A_T + so, Ah + ga);
            cpa16(stg + 1 * A_T + so, Al + ga);
            cpa16(stg + 2 * A_T + so, Bh + gb);
            cpa16(stg + 3 * A_T + so, Bl + gb);
        }
    };

    fill(0); cpa_commit();
    fill(1); cpa_commit();

    // lane-constant ldmatrix address components (s8 k32 frag == b16 k16 pattern)
    const int arow = wm + (lane & 15);
    const int achi = lane >> 4;
    const int brow = (lane & 7) + 8 * (lane >> 4);
    const int bchi = (lane >> 3) & 1;

    for (int ck = 0; ck < NC; ++ck) {
        cpa_wait1();                    // chunk ck's group complete
        __syncthreads();                // cross-thread visibility + stage reuse

        const uint32_t stg = sbase + (uint32_t)(ck % 3) * STG_B;
        const uint32_t sAh = stg, sAl = stg + A_T;
        const uint32_t sBh = stg + 2 * A_T, sBl = stg + 3 * A_T;

        #pragma unroll
        for (int ks = 0; ks < 4; ++ks) {    // 4 x k32 per 128-chunk
            uint32_t fah[4][4], fal[4][4], fbh[4][2], fbl[4][2];
            #pragma unroll
            for (int mt = 0; mt < 4; ++mt) {
                const int r = arow + mt * 16;
                const int c = ks * 2 + achi;
                const uint32_t off = (uint32_t)(r * 128 + ((c ^ (r & 7)) << 4));
                ldsm4(fah[mt][0], fah[mt][1], fah[mt][2], fah[mt][3], sAh + off);
                ldsm4(fal[mt][0], fal[mt][1], fal[mt][2], fal[mt][3], sAl + off);
            }
            #pragma unroll
            for (int nb2 = 0; nb2 < 2; ++nb2) {   // 16 N-cols per ldsm.x4
                const int r = wn + nb2 * 16 + brow;
                const int c = ks * 2 + bchi;
                const uint32_t off = (uint32_t)(r * 128 + ((c ^ (r & 7)) << 4));
                uint32_t q0, q1, q2, q3;
                ldsm4(q0, q1, q2, q3, sBh + off);
                fbh[nb2 * 2][0] = q0; fbh[nb2 * 2][1] = q1;
                fbh[nb2 * 2 + 1][0] = q2; fbh[nb2 * 2 + 1][1] = q3;
                ldsm4(q0, q1, q2, q3, sBl + off);
                fbl[nb2 * 2][0] = q0; fbl[nb2 * 2][1] = q1;
                fbl[nb2 * 2 + 1][0] = q2; fbl[nb2 * 2 + 1][1] = q3;
            }
            // term-major: consecutive mma never share an accumulator
            #pragma unroll
            for (int mt = 0; mt < 4; ++mt)
                #pragma unroll
                for (int nb = 0; nb < 4; ++nb)
                    mma_s8(acc1[mt][nb], fah[mt], fbh[nb]);
            #pragma unroll
            for (int mt = 0; mt < 4; ++mt)
                #pragma unroll
                for (int nb = 0; nb < 4; ++nb)
                    mma_s8(acc2[mt][nb], fah[mt], fbl[nb]);
            #pragma unroll
            for (int mt = 0; mt < 4; ++mt)
                #pragma unroll
                for (int nb = 0; nb < 4; ++nb)
                    mma_s8(acc2[mt][nb], fal[mt], fbh[nb]);
        }

        if (ck + 2 < NC) fill(ck + 2);  // after compute: stage safe (post-bar)
        cpa_commit();                   // uniform group count per iter
    }

    // epilogue: C = sa*sb*(16384*acc1 + 128*acc2)
    const int g  = lane >> 2;
    const int i2 = (lane & 3) * 2;
    #pragma unroll
    for (int mt = 0; mt < 4; ++mt) {
        const int row = row0 + wm + mt * 16 + g;
        const float sa0 = sa[row], sa1 = sa[row + 8];
        #pragma unroll
        for (int nb = 0; nb < 4; ++nb) {
            const int col = col0 + wn + nb * 8 + i2;
            const float sb0 = sbv[col], sb1 = sbv[col + 1];
            float v0 = fmaf(128.f, (float)acc1[mt][nb][0], (float)acc2[mt][nb][0]) * 128.f;
            float v1 = fmaf(128.f, (float)acc1[mt][nb][1], (float)acc2[mt][nb][1]) * 128.f;
            float v2 = fmaf(128.f, (float)acc1[mt][nb][2], (float)acc2[mt][nb][2]) * 128.f;
            float v3 = fmaf(128.f, (float)acc1[mt][nb][3], (float)acc2[mt][nb][3]) * 128.f;
            float* p  = C + (size_t)row * Nld + col;
            float* p2 = C + (size_t)(row + 8) * Nld + col;
            *(float2*)p  = make_float2(v0 * sa0 * sb0, v1 * sa0 * sb1);
            *(float2*)p2 = make_float2(v2 * sa1 * sb0, v3 * sa1 * sb1);
        }
    }
}

// ---------------- per-row quantize: A[row,:] -> int8 hi/lo + scale ----------
__global__ void __launch_bounds__(256)
qrows(const float* __restrict__ A, int K,
      int8_t* __restrict__ qh, int8_t* __restrict__ ql, float* __restrict__ sa)
{
    __shared__ float red[256];
    const int row = blockIdx.x;
    const int tid = threadIdx.x;
    const float* a = A + (size_t)row * K;

    float m = 0.0f;
    for (int k = tid; k < K; k += 256) m = fmaxf(m, fabsf(a[k]));
    red[tid] = m; __syncthreads();
    #pragma unroll
    for (int s = 128; s > 0; s >>= 1) {
        if (tid < s) red[tid] = fmaxf(red[tid], red[tid + s]);
        __syncthreads();
    }
    m = fmaxf(red[0], 1e-30f);
    const float sc = QLEV / m;

    for (int k = tid; k < K; k += 256) {
        const int q  = __float2int_rn(a[k] * sc);
        const int hi = (q + 64) >> 7;
        const int lo = q - (hi << 7);
        qh[(size_t)row * K + k] = (int8_t)hi;
        ql[(size_t)row * K + k] = (int8_t)lo;
    }
    if (tid == 0) sa[row] = m * (1.0f / QLEV);
}

// ---------------- per-col max of W[K,N] -> scale ----------------------------
__global__ void __launch_bounds__(256)
colmax(const float* __restrict__ W, int K, int N, float* __restrict__ sbv)
{
    __shared__ float red[8][32];
    const int n  = blockIdx.x * 32 + threadIdx.x;
    float m = 0.0f;
    for (int k = threadIdx.y; k < K; k += 8)
        m = fmaxf(m, fabsf(W[(size_t)k * N + n]));
    red[threadIdx.y][threadIdx.x] = m; __syncthreads();
    if (threadIdx.y == 0) {
        #pragma unroll
        for (int j = 1; j < 8; ++j) m = fmaxf(m, red[j][threadIdx.x]);
        sbv[n] = fmaxf(m, 1e-30f) * (1.0f / QLEV);
    }
}

// ---------------- transpose + quantize: W[K,N] -> q[N][K] hi/lo -------------
__global__ void __launch_bounds__(256)
quant_t(const float* __restrict__ W, int K, int N, const float* __restrict__ sbv,
        int8_t* __restrict__ qh, int8_t* __restrict__ ql)
{
    __shared__ float tile[32][33];
    const int n0 = blockIdx.x * 32, k0 = blockIdx.y * 32;
    const int tx = threadIdx.x, ty = threadIdx.y;   // (32, 8)
    #pragma unroll
    for (int r = 0; r < 4; ++r)
        tile[ty + 8 * r][tx] = W[(size_t)(k0 + ty + 8 * r) * N + n0 + tx];
    __syncthreads();
    #pragma unroll
    for (int r = 0; r < 4; ++r) {
        const int n = n0 + ty + 8 * r, k = k0 + tx;
        const float v = tile[tx][ty + 8 * r];
        const int q  = __float2int_rn(v / sbv[n]);
        const int hi = (q + 64) >> 7;
        const int lo = q - (hi << 7);
        qh[(size_t)n * K + k] = (int8_t)hi;
        ql[(size_t)n * K + k] = (int8_t)lo;
    }
}

// ---------------- SRU recurrence --------------------------------------------
__device__ __forceinline__ float sigmoidf_(float x) {
    return 1.0f / (1.0f + expf(-x));
}

template <bool RESID_FROM_U>
__global__ void __launch_bounds__(HID)
sru_layer_kernel(const float* __restrict__ U, int ustride,
                 const float* __restrict__ resid_h,
                 const float* __restrict__ vc, const float* __restrict__ bias,
                 float* __restrict__ h_out)
{
    const int d = threadIdx.x;
    const int b = blockIdx.x;

    const float vf = vc[d],   vr = vc[HID + d];
    const float bf = bias[d], br = bias[HID + d];

    const float* Ub = U + (size_t)b * T_STEPS * ustride;
    const float* rb = RESID_FROM_U ? nullptr : (resid_h + (size_t)b * T_STEPS * HID);
    float* hb = h_out + (size_t)b * T_STEPS * HID;

    float c = 0.0f;
    #pragma unroll
    for (int t = 0; t < T_STEPS; ++t) {
        const float* Ut = Ub + (size_t)t * ustride;
        const float u0 = Ut[d];
        const float u1 = Ut[HID + d];
        const float u2 = Ut[2 * HID + d];
        const float xt = RESID_FROM_U ? Ut[3 * HID + d] : rb[(size_t)t * HID + d];

        const float f = sigmoidf_(u1 + vf * c + bf);
        c = f * c + (1.0f - f) * u0;
        const float r = sigmoidf_(u2 + vr * c + br);
        hb[(size_t)t * HID + d] = r * tanhf(c) + (1.0f - r) * xt * SCALE_X;
    }
}

// ---- final SRU layer fused with the t-mean ---------------------------------
__global__ void __launch_bounds__(HID)
sru_layer_mean_kernel(const float* __restrict__ U, int ustride,
                      const float* __restrict__ resid_h,
                      const float* __restrict__ vc, const float* __restrict__ bias,
                      float* __restrict__ hbar)
{
    const int d = threadIdx.x;
    const int b = blockIdx.x;

    const float vf = vc[d],   vr = vc[HID + d];
    const float bf = bias[d], br = bias[HID + d];

    const float* Ub = U + (size_t)b * T_STEPS * ustride;
    const float* rb = resid_h + (size_t)b * T_STEPS * HID;

    float c = 0.0f, s = 0.0f;
    #pragma unroll
    for (int t = 0; t < T_STEPS; ++t) {
        const float* Ut = Ub + (size_t)t * ustride;
        const float u0 = Ut[d];
        const float u1 = Ut[HID + d];
        const float u2 = Ut[2 * HID + d];
        const float xt = rb[(size_t)t * HID + d];

        const float f = sigmoidf_(u1 + vf * c + bf);
        c = f * c + (1.0f - f) * u0;
        const float r = sigmoidf_(u2 + vr * c + br);
        s += r * tanhf(c) + (1.0f - r) * xt * SCALE_X;
    }
    hbar[(size_t)b * HID + d] = s * (1.0f / T_STEPS);
}

// ---------------- FC head ----------------------------------------------------
__global__ void __launch_bounds__(256)
fc_kernel(const float* __restrict__ hbar, const float* __restrict__ w,
          const float* __restrict__ bias, float* __restrict__ out)
{
    __shared__ float hrow[HID];
    __shared__ float part[4][64];
    const int b   = blockIdx.x;
    const int tid = threadIdx.x;

    #pragma unroll
    for (int i = tid; i < HID; i += 256) hrow[i] = hbar[(size_t)b * HID + i];
    __syncthreads();

    const int c  = tid & 63;
    const int sl = tid >> 6;
    float s = 0.0f;
    if (c < NCLS) {
        const int d0 = sl * 256;
        #pragma unroll 8
        for (int d = d0; d < d0 + 256; ++d)
            s = fmaf(hrow[d], w[(size_t)d * NCLS + c], s);
    }
    part[sl][c] = s;
    __syncthreads();

    if (tid < NCLS)
        out[(size_t)b * NCLS + tid] =
            part[0][tid] + part[1][tid] + part[2][tid] + part[3][tid] + bias[tid];
}

// ---------------- launch -----------------------------------------------------
extern "C" void kernel_launch(void* const* d_in, const int* in_sizes, int n_in,
                              void* d_out, int out_size)
{
    const float* x    = (const float*)d_in[0];
    const float* W0   = (const float*)d_in[1];
    const float* W1   = (const float*)d_in[2];
    const float* W2   = (const float*)d_in[3];
    const float* vc0  = (const float*)d_in[4];
    const float* vc1  = (const float*)d_in[5];
    const float* vc2  = (const float*)d_in[6];
    const float* b0   = (const float*)d_in[7];
    const float* b1   = (const float*)d_in[8];
    const float* b2   = (const float*)d_in[9];
    const float* fcw  = (const float*)d_in[10];
    const float* fcb  = (const float*)d_in[11];
    float* out = (float*)d_out;

    float *U, *h0, *h1, *hbar, *sa, *sb;
    int8_t *qah, *qal, *qbh, *qbl;
    cudaGetSymbolAddress((void**)&U,    g_U);
    cudaGetSymbolAddress((void**)&h0,   g_h0);
    cudaGetSymbolAddress((void**)&h1,   g_h1);
    cudaGetSymbolAddress((void**)&hbar, g_hbar);
    cudaGetSymbolAddress((void**)&qah,  g_qa_hi);
    cudaGetSymbolAddress((void**)&qal,  g_qa_lo);
    cudaGetSymbolAddress((void**)&qbh,  g_qb_hi);
    cudaGetSymbolAddress((void**)&qbl,  g_qb_lo);
    cudaGetSymbolAddress((void**)&sa,   g_sa);
    cudaGetSymbolAddress((void**)&sb,   g_sb);

    cudaFuncSetAttribute(gemm_s8x3,
                         cudaFuncAttributeMaxDynamicSharedMemorySize, SMEM_GEMM);

    // Layer 0: U = x @ W0  (M=24576, N=4096, K=512)
    qrows<<<MROWS, 256>>>(x, IMG, qah, qal, sa);
    colmax<<<4096 / 32, dim3(32, 8)>>>(W0, IMG, 4096, sb);
    quant_t<<<dim3(4096 / 32, IMG / 32), dim3(32, 8)>>>(W0, IMG, 4096, sb, qbh, qbl);
    gemm_s8x3<<<dim3(4096 / 128, MROWS / 128), 256, SMEM_GEMM>>>(
        qah, qal, qbh, qbl, sa, sb, U, IMG, 4096);
    sru_layer_kernel<true><<<B_SZ, HID>>>(U, 4096, nullptr, vc0, b0, h0);

    // Layer 1: U = h0 @ W1 (N=3072, K=1024)
    qrows<<<MROWS, 256>>>(h0, HID, qah, qal, sa);
    colmax<<<3072 / 32, dim3(32, 8)>>>(W1, HID, 3072, sb);
    quant_t<<<dim3(3072 / 32, HID / 32), dim3(32, 8)>>>(W1, HID, 3072, sb, qbh, qbl);
    gemm_s8x3<<<dim3(3072 / 128, MROWS / 128), 256, SMEM_GEMM>>>(
        qah, qal, qbh, qbl, sa, sb, U, HID, 3072);
    sru_layer_kernel<false><<<B_SZ, HID>>>(U, 3072, h0, vc1, b1, h1);

    // Layer 2: U = h1 @ W2; fused recurrence + t-mean
    qrows<<<MROWS, 256>>>(h1, HID, qah, qal, sa);
    colmax<<<3072 / 32, dim3(32, 8)>>>(W2, HID, 3072, sb);
    quant_t<<<dim3(3072 / 32, HID / 32), dim3(32, 8)>>>(W2, HID, 3072, sb, qbh, qbl);
    gemm_s8x3<<<dim3(3072 / 128, MROWS / 128), 256, SMEM_GEMM>>>(
        qah, qal, qbh, qbl, sa, sb, U, HID, 3072);
    sru_layer_mean_kernel<<<B_SZ, HID>>>(U, 3072, h1, vc2, b2, hbar);

    // FC head on time-averaged h (mean commutes with the linear head)
    fc_kernel<<<B_SZ, 256>>>(hbar, fcw, fcb, out);
}

// round 15
// speedup vs baseline: 3.8232x; 3.8232x over previous
#include <cuda_runtime.h>
#include <cuda_fp16.h>
#include <math.h>
#include <stdint.h>

#define T_STEPS 12
#define HID     1024
#define B_SZ    2048
#define IMG     512
#define NCLS    51
#define MROWS   (T_STEPS * B_SZ)   /* 24576; row r = b*T + t */

#define SCALE_X 1.7320508075688772f  /* sqrt(3) */

// ---------------- scratch (device globals; no allocations allowed) ----------
__device__ __align__(256) float g_U [(size_t)MROWS * 4096];
__device__ __align__(256) float g_h0[(size_t)MROWS * HID];
__device__ __align__(256) float g_h1[(size_t)MROWS * HID];
__device__ __align__(256) float g_hbar[(size_t)B_SZ * HID];
// fp16 hi/lo split of activations (A is exact to ~2^-24)
__device__ __align__(256) __half g_ah[(size_t)MROWS * HID];
__device__ __align__(256) __half g_al[(size_t)MROWS * HID];
// fp16 transposed weights [N][K] (single precision term; max 4096x1024)
__device__ __align__(256) __half g_wt[(size_t)4096 * 1024];

// ======================= arch-neutral PTX helpers ===========================
__device__ __forceinline__ uint32_t smem_u32(const void* p) {
    uint32_t a;
    asm("{ .reg .u64 t; cvta.to.shared.u64 t, %1; cvt.u32.u64 %0, t; }"
        : "=r"(a) : "l"(p));
    return a;
}
__device__ __forceinline__ void cpa16(uint32_t dst, const void* src) {
    asm volatile("cp.async.cg.shared.global [%0], [%1], 16;"
                 :: "r"(dst), "l"(src) : "memory");
}
__device__ __forceinline__ void cpa_commit() {
    asm volatile("cp.async.commit_group;" ::: "memory");
}
__device__ __forceinline__ void cpa_wait1() {
    asm volatile("cp.async.wait_group 1;" ::: "memory");
}
__device__ __forceinline__ void ldsm4(uint32_t& r0, uint32_t& r1,
                                      uint32_t& r2, uint32_t& r3, uint32_t addr) {
    asm volatile("ldmatrix.sync.aligned.m8n8.x4.shared.b16 {%0,%1,%2,%3}, [%4];"
                 : "=r"(r0), "=r"(r1), "=r"(r2), "=r"(r3) : "r"(addr));
}
__device__ __forceinline__ void mma_f16(float* c, const uint32_t* a,
                                        const uint32_t* b) {
    asm volatile(
        "mma.sync.aligned.m16n8k16.row.col.f32.f16.f16.f32 "
        "{%0,%1,%2,%3}, {%4,%5,%6,%7}, {%8,%9}, {%0,%1,%2,%3};"
        : "+f"(c[0]), "+f"(c[1]), "+f"(c[2]), "+f"(c[3])
        : "r"(a[0]), "r"(a[1]), "r"(a[2]), "r"(a[3]), "r"(b[0]), "r"(b[1]));
}

// ======================= fp16x2-A tensor-core GEMM ==========================
// C[M,N] (fp32) = (Ah + Al) * B   (A split hi/lo fp16 = exact; B single fp16).
// A: [M,K] row-major; B: [N,K] row-major (pre-transposed -> mma row.col).
// CTA tile 128x256, BK=64 (128B rows, XOR swizzle), 8 warps of 64x64,
// 2-stage cp.async pipeline. grid = (N/256, M/128), 256 threads.
#define A_TILE      16384                   /* 128 rows x 128 B */
#define B_TILE      32768                   /* 256 rows x 128 B */
#define STAGE_BYTES (2 * A_TILE + B_TILE)   /* Ah, Al, B = 64 KB */
#define SMEM_GEMM   (2 * STAGE_BYTES)       /* 128 KB */

__global__ void __launch_bounds__(256)
gemm_f16x2(const __half* __restrict__ Ah, const __half* __restrict__ Al,
           const __half* __restrict__ Bm,
           float* __restrict__ C, int K, int Nld)
{
    extern __shared__ char smem[];
    const uint32_t sb = smem_u32(smem);
    const int tid  = threadIdx.x;
    const int lane = tid & 31;
    const int wid  = tid >> 5;
    const int row0 = blockIdx.y * 128;
    const int col0 = blockIdx.x * 256;
    const int wm   = (wid >> 2) * 64;   // warp M offset (0 / 64)
    const int wn   = (wid & 3) * 64;    // warp N offset (0..192)

    const int NC = K >> 6;              // K/64 chunks

    float acc[4][8][4];
    #pragma unroll
    for (int i = 0; i < 4; ++i)
        #pragma unroll
        for (int j = 0; j < 8; ++j)
            #pragma unroll
            for (int q = 0; q < 4; ++q) acc[i][j][q] = 0.0f;

    // ---- stage fill: A hi/lo 2x(128x8) + B (256x8) 16B chunks; 16/thread
    auto fill = [&](int ck) {
        const int k0 = ck << 6;
        const uint32_t stg = sb + (uint32_t)(ck & 1) * STAGE_BYTES;
        #pragma unroll
        for (int i = 0; i < 8; ++i) {            // A: 2048 chunks (hi+lo)
            const int lin  = tid + i * 256;      // 0..2047
            const int tl   = lin >> 10;          // 0 = hi, 1 = lo
            const int r    = (lin >> 3) & 127;
            const int c    = lin & 7;
            const uint32_t so = (uint32_t)(r * 128 + ((c ^ (r & 7)) << 4));
            const size_t  go = (size_t)(row0 + r) * K + k0 + c * 8;
            cpa16(stg + (uint32_t)tl * A_TILE + so, (tl ? Al : Ah) + go);
        }
        #pragma unroll
        for (int i = 0; i < 8; ++i) {            // B: 2048 chunks
            const int lin  = tid + i * 256;      // 0..2047
            const int r    = lin >> 3;           // row 0..255
            const int c    = lin & 7;
            const uint32_t so = (uint32_t)(r * 128 + ((c ^ (r & 7)) << 4));
            const size_t  go = (size_t)(col0 + r) * K + k0 + c * 8;
            cpa16(stg + 2 * A_TILE + so, Bm + go);
        }
    };

    fill(0); cpa_commit();

    // lane-constant ldmatrix address components
    const int arow = wm + (lane & 15);               // A row within tile
    const int achi = lane >> 4;                      // A k-chunk hi bit
    const int brow = (lane & 7) + 8 * (lane >> 4);   // B row within 16-col group
    const int bchi = (lane >> 3) & 1;                // B k-chunk hi bit

    for (int ck = 0; ck < NC; ++ck) {
        if (ck + 1 < NC) fill(ck + 1);
        cpa_commit();                   // uniform group count (may be empty)
        cpa_wait1();                    // group for chunk ck complete
        __syncthreads();

        const uint32_t stg = sb + (uint32_t)(ck & 1) * STAGE_BYTES;
        const uint32_t sAh = stg, sAl = stg + A_TILE;
        const uint32_t sB  = stg + 2 * A_TILE;

        #pragma unroll
        for (int ks = 0; ks < 4; ++ks) {    // 4 x k16 per 64-chunk
            uint32_t fah[4][4], fal[4][4], fb[8][2];
            #pragma unroll
            for (int mt = 0; mt < 4; ++mt) {
                const int r = arow + mt * 16;
                const int c = ks * 2 + achi;
                const uint32_t off = (uint32_t)(r * 128 + ((c ^ (r & 7)) << 4));
                ldsm4(fah[mt][0], fah[mt][1], fah[mt][2], fah[mt][3], sAh + off);
                ldsm4(fal[mt][0], fal[mt][1], fal[mt][2], fal[mt][3], sAl + off);
            }
            #pragma unroll
            for (int nb2 = 0; nb2 < 4; ++nb2) {   // 16 N-cols per ldsm.x4
                const int r = wn + nb2 * 16 + brow;
                const int c = ks * 2 + bchi;
                const uint32_t off = (uint32_t)(r * 128 + ((c ^ (r & 7)) << 4));
                ldsm4(fb[nb2 * 2][0], fb[nb2 * 2][1],
                      fb[nb2 * 2 + 1][0], fb[nb2 * 2 + 1][1], sB + off);
            }
            // term-major: consecutive mma never share an accumulator
            #pragma unroll
            for (int mt = 0; mt < 4; ++mt)
                #pragma unroll
                for (int nb = 0; nb < 8; ++nb)
                    mma_f16(acc[mt][nb], fah[mt], fb[nb]);
            #pragma unroll
            for (int mt = 0; mt < 4; ++mt)
                #pragma unroll
                for (int nb = 0; nb < 8; ++nb)
                    mma_f16(acc[mt][nb], fal[mt], fb[nb]);
        }
        __syncthreads();                // stage free before next fill
    }

    // ---- epilogue: direct fp32 stores (frag: rows g,g+8; cols 2i,2i+1)
    const int g  = lane >> 2;
    const int i2 = (lane & 3) * 2;
    #pragma unroll
    for (int mt = 0; mt < 4; ++mt) {
        #pragma unroll
        for (int nb = 0; nb < 8; ++nb) {
            const int row = row0 + wm + mt * 16 + g;
            const int col = col0 + wn + nb * 8 + i2;
            float* p  = C + (size_t)row * Nld + col;
            float* p2 = C + (size_t)(row + 8) * Nld + col;
            *(float2*)p  = make_float2(acc[mt][nb][0], acc[mt][nb][1]);
            *(float2*)p2 = make_float2(acc[mt][nb][2], acc[mt][nb][3]);
        }
    }
}

// ---------------- fp32 -> fp16 hi/lo split ----------------------------------
__global__ void split_f32(const float* __restrict__ a,
                          __half* __restrict__ hi, __half* __restrict__ lo)
{
    const int i = blockIdx.x * blockDim.x + threadIdx.x;
    const float v = a[i];
    const __half h = __float2half(v);
    hi[i] = h;
    lo[i] = __float2half(v - __half2float(h));
}

// ---------------- weight transpose + convert: W[K,N] -> Wt[N][K] fp16 ------
__global__ void __launch_bounds__(256)
wconv_t(const float* __restrict__ W, int K, int N, __half* __restrict__ Wt)
{
    __shared__ float tile[32][33];
    const int n0 = blockIdx.x * 32, k0 = blockIdx.y * 32;
    const int tx = threadIdx.x, ty = threadIdx.y;   // (32, 8)
    #pragma unroll
    for (int r = 0; r < 4; ++r)
        tile[ty + 8 * r][tx] = W[(size_t)(k0 + ty + 8 * r) * N + n0 + tx];
    __syncthreads();
    #pragma unroll
    for (int r = 0; r < 4; ++r) {
        const int n = n0 + ty + 8 * r, k = k0 + tx;
        Wt[(size_t)n * K + k] = __float2half(tile[tx][ty + 8 * r]);
    }
}

// ---------------- SRU recurrence (optionally emits fp16 split of h) ---------
__device__ __forceinline__ float sigmoidf_(float x) {
    return 1.0f / (1.0f + expf(-x));
}

template <bool RESID_FROM_U, bool WRITE_SPLIT>
__global__ void __launch_bounds__(HID)
sru_layer_kernel(const float* __restrict__ U, int ustride,
                 const float* __restrict__ resid_h,
                 const float* __restrict__ vc, const float* __restrict__ bias,
                 float* __restrict__ h_out,
                 __half* __restrict__ hh, __half* __restrict__ hl)
{
    const int d = threadIdx.x;
    const int b = blockIdx.x;

    const float vf = vc[d],   vr = vc[HID + d];
    const float bf = bias[d], br = bias[HID + d];

    const float* Ub = U + (size_t)b * T_STEPS * ustride;
    const float* rb = RESID_FROM_U ? nullptr : (resid_h + (size_t)b * T_STEPS * HID);
    const size_t ob = (size_t)b * T_STEPS * HID;

    float c = 0.0f;
    #pragma unroll
    for (int t = 0; t < T_STEPS; ++t) {
        const float* Ut = Ub + (size_t)t * ustride;
        const float u0 = Ut[d];
        const float u1 = Ut[HID + d];
        const float u2 = Ut[2 * HID + d];
        const float xt = RESID_FROM_U ? Ut[3 * HID + d] : rb[(size_t)t * HID + d];

        const float f = sigmoidf_(u1 + vf * c + bf);
        c = f * c + (1.0f - f) * u0;
        const float r = sigmoidf_(u2 + vr * c + br);
        const float h = r * tanhf(c) + (1.0f - r) * xt * SCALE_X;
        const size_t o = ob + (size_t)t * HID + d;
        h_out[o] = h;
        if (WRITE_SPLIT) {
            const __half hi = __float2half(h);
            hh[o] = hi;
            hl[o] = __float2half(h - __half2float(hi));
        }
    }
}

// ---- final SRU layer fused with the t-mean: only hbar is materialized ------
__global__ void __launch_bounds__(HID)
sru_layer_mean_kernel(const float* __restrict__ U, int ustride,
                      const float* __restrict__ resid_h,
                      const float* __restrict__ vc, const float* __restrict__ bias,
                      float* __restrict__ hbar)
{
    const int d = threadIdx.x;
    const int b = blockIdx.x;

    const float vf = vc[d],   vr = vc[HID + d];
    const float bf = bias[d], br = bias[HID + d];

    const float* Ub = U + (size_t)b * T_STEPS * ustride;
    const float* rb = resid_h + (size_t)b * T_STEPS * HID;

    float c = 0.0f, s = 0.0f;
    #pragma unroll
    for (int t = 0; t < T_STEPS; ++t) {
        const float* Ut = Ub + (size_t)t * ustride;
        const float u0 = Ut[d];
        const float u1 = Ut[HID + d];
        const float u2 = Ut[2 * HID + d];
        const float xt = rb[(size_t)t * HID + d];

        const float f = sigmoidf_(u1 + vf * c + bf);
        c = f * c + (1.0f - f) * u0;
        const float r = sigmoidf_(u2 + vr * c + br);
        s += r * tanhf(c) + (1.0f - r) * xt * SCALE_X;
    }
    hbar[(size_t)b * HID + d] = s * (1.0f / T_STEPS);
}

// ---------------- FC head ----------------------------------------------------
__global__ void __launch_bounds__(256)
fc_kernel(const float* __restrict__ hbar, const float* __restrict__ w,
          const float* __restrict__ bias, float* __restrict__ out)
{
    __shared__ float hrow[HID];
    __shared__ float part[4][64];
    const int b   = blockIdx.x;
    const int tid = threadIdx.x;

    #pragma unroll
    for (int i = tid; i < HID; i += 256) hrow[i] = hbar[(size_t)b * HID + i];
    __syncthreads();

    const int c  = tid & 63;
    const int sl = tid >> 6;
    float s = 0.0f;
    if (c < NCLS) {
        const int d0 = sl * 256;
        #pragma unroll 8
        for (int d = d0; d < d0 + 256; ++d)
            s = fmaf(hrow[d], w[(size_t)d * NCLS + c], s);
    }
    part[sl][c] = s;
    __syncthreads();

    if (tid < NCLS)
        out[(size_t)b * NCLS + tid] =
            part[0][tid] + part[1][tid] + part[2][tid] + part[3][tid] + bias[tid];
}

// ---------------- launch -----------------------------------------------------
extern "C" void kernel_launch(void* const* d_in, const int* in_sizes, int n_in,
                              void* d_out, int out_size)
{
    const float* x    = (const float*)d_in[0];
    const float* W0   = (const float*)d_in[1];
    const float* W1   = (const float*)d_in[2];
    const float* W2   = (const float*)d_in[3];
    const float* vc0  = (const float*)d_in[4];
    const float* vc1  = (const float*)d_in[5];
    const float* vc2  = (const float*)d_in[6];
    const float* b0   = (const float*)d_in[7];
    const float* b1   = (const float*)d_in[8];
    const float* b2   = (const float*)d_in[9];
    const float* fcw  = (const float*)d_in[10];
    const float* fcb  = (const float*)d_in[11];
    float* out = (float*)d_out;

    float *U, *h0, *h1, *hbar;
    __half *ah, *al, *wt;
    cudaGetSymbolAddress((void**)&U,    g_U);
    cudaGetSymbolAddress((void**)&h0,   g_h0);
    cudaGetSymbolAddress((void**)&h1,   g_h1);
    cudaGetSymbolAddress((void**)&hbar, g_hbar);
    cudaGetSymbolAddress((void**)&ah,   g_ah);
    cudaGetSymbolAddress((void**)&al,   g_al);
    cudaGetSymbolAddress((void**)&wt,   g_wt);

    cudaFuncSetAttribute(gemm_f16x2,
                         cudaFuncAttributeMaxDynamicSharedMemorySize, SMEM_GEMM);

    // Layer 0: U = x @ W0  (M=24576, N=4096, K=512)
    split_f32<<<(MROWS * IMG) / 256, 256>>>(x, ah, al);
    wconv_t<<<dim3(4096 / 32, IMG / 32), dim3(32, 8)>>>(W0, IMG, 4096, wt);
    gemm_f16x2<<<dim3(4096 / 256, MROWS / 128), 256, SMEM_GEMM>>>(
        ah, al, wt, U, IMG, 4096);
    sru_layer_kernel<true, true><<<B_SZ, HID>>>(U, 4096, nullptr, vc0, b0, h0, ah, al);

    // Layer 1: U = h0 @ W1 (N=3072, K=1024)
    wconv_t<<<dim3(3072 / 32, HID / 32), dim3(32, 8)>>>(W1, HID, 3072, wt);
    gemm_f16x2<<<dim3(3072 / 256, MROWS / 128), 256, SMEM_GEMM>>>(
        ah, al, wt, U, HID, 3072);
    sru_layer_kernel<false, true><<<B_SZ, HID>>>(U, 3072, h0, vc1, b1, h1, ah, al);

    // Layer 2: U = h1 @ W2; fused recurrence + t-mean (h never materialized)
    wconv_t<<<dim3(3072 / 32, HID / 32), dim3(32, 8)>>>(W2, HID, 3072, wt);
    gemm_f16x2<<<dim3(3072 / 256, MROWS / 128), 256, SMEM_GEMM>>>(
        ah, al, wt, U, HID, 3072);
    sru_layer_mean_kernel<<<B_SZ, HID>>>(U, 3072, h1, vc2, b2, hbar);

    // FC head on time-averaged h (mean commutes with the linear head)
    fc_kernel<<<B_SZ, 256>>>(hbar, fcw, fcb, out);
}

// round 16
// speedup vs baseline: 5.6548x; 1.4791x over previous
#include <cuda_runtime.h>
#include <cuda_fp16.h>
#include <math.h>
#include <stdint.h>

#define T_STEPS 12
#define HID     1024
#define B_SZ    2048
#define IMG     512
#define NCLS    51
#define MROWS   (T_STEPS * B_SZ)   /* 24576; row r = b*T + t */

#define SCALE_X 1.7320508075688772f  /* sqrt(3) */

// ---------------- scratch (device globals; no allocations allowed) ----------
__device__ __align__(256) float g_U [(size_t)MROWS * 4096];
__device__ __align__(256) float g_h0[(size_t)MROWS * HID];
__device__ __align__(256) float g_h1[(size_t)MROWS * HID];
__device__ __align__(256) float g_hbar[(size_t)B_SZ * HID];
// fp16 activations (single precision term)
__device__ __align__(256) __half g_a16[(size_t)MROWS * HID];
// fp16 transposed weights [N][K] (max 4096x1024)
__device__ __align__(256) __half g_wt[(size_t)4096 * 1024];

// ======================= arch-neutral PTX helpers ===========================
__device__ __forceinline__ uint32_t smem_u32(const void* p) {
    uint32_t a;
    asm("{ .reg .u64 t; cvta.to.shared.u64 t, %1; cvt.u32.u64 %0, t; }"
        : "=r"(a) : "l"(p));
    return a;
}
__device__ __forceinline__ void cpa16(uint32_t dst, const void* src) {
    asm volatile("cp.async.cg.shared.global [%0], [%1], 16;"
                 :: "r"(dst), "l"(src) : "memory");
}
__device__ __forceinline__ void cpa_commit() {
    asm volatile("cp.async.commit_group;" ::: "memory");
}
__device__ __forceinline__ void cpa_wait1() {
    asm volatile("cp.async.wait_group 1;" ::: "memory");
}
__device__ __forceinline__ void ldsm4(uint32_t& r0, uint32_t& r1,
                                      uint32_t& r2, uint32_t& r3, uint32_t addr) {
    asm volatile("ldmatrix.sync.aligned.m8n8.x4.shared.b16 {%0,%1,%2,%3}, [%4];"
                 : "=r"(r0), "=r"(r1), "=r"(r2), "=r"(r3) : "r"(addr));
}
__device__ __forceinline__ void mma_f16(float* c, const uint32_t* a,
                                        const uint32_t* b) {
    asm volatile(
        "mma.sync.aligned.m16n8k16.row.col.f32.f16.f16.f32 "
        "{%0,%1,%2,%3}, {%4,%5,%6,%7}, {%8,%9}, {%0,%1,%2,%3};"
        : "+f"(c[0]), "+f"(c[1]), "+f"(c[2]), "+f"(c[3])
        : "r"(a[0]), "r"(a[1]), "r"(a[2]), "r"(a[3]), "r"(b[0]), "r"(b[1]));
}

// ======================= fp16 tensor-core GEMM ==============================
// C[M,N] (fp32) = A * B, fp16 operands, fp32 accumulate.
// A: [M,K] row-major; B: [N,K] row-major (pre-transposed -> mma row.col).
// CTA tile 128x256, BK=64 (128B rows, XOR swizzle), 8 warps of 64x64,
// 2-stage cp.async pipeline. grid = (N/256, M/128), 256 threads.
#define A_TILE      16384                   /* 128 rows x 128 B */
#define B_TILE      32768                   /* 256 rows x 128 B */
#define STAGE_BYTES (A_TILE + B_TILE)       /* 48 KB */
#define SMEM_GEMM   (2 * STAGE_BYTES)       /* 96 KB */

__global__ void __launch_bounds__(256)
gemm_f16(const __half* __restrict__ Am, const __half* __restrict__ Bm,
         float* __restrict__ C, int K, int Nld)
{
    extern __shared__ char smem[];
    const uint32_t sb = smem_u32(smem);
    const int tid  = threadIdx.x;
    const int lane = tid & 31;
    const int wid  = tid >> 5;
    const int row0 = blockIdx.y * 128;
    const int col0 = blockIdx.x * 256;
    const int wm   = (wid >> 2) * 64;   // warp M offset (0 / 64)
    const int wn   = (wid & 3) * 64;    // warp N offset (0..192)

    const int NC = K >> 6;              // K/64 chunks

    float acc[4][8][4];
    #pragma unroll
    for (int i = 0; i < 4; ++i)
        #pragma unroll
        for (int j = 0; j < 8; ++j)
            #pragma unroll
            for (int q = 0; q < 4; ++q) acc[i][j][q] = 0.0f;

    // ---- stage fill: A (128x8) + B (256x8) 16B chunks; 12 cp.async/thread
    auto fill = [&](int ck) {
        const int k0 = ck << 6;
        const uint32_t stg = sb + (uint32_t)(ck & 1) * STAGE_BYTES;
        #pragma unroll
        for (int i = 0; i < 4; ++i) {            // A: 1024 chunks
            const int lin  = tid + i * 256;      // 0..1023
            const int r    = lin >> 3;
            const int c    = lin & 7;
            const uint32_t so = (uint32_t)(r * 128 + ((c ^ (r & 7)) << 4));
            const size_t  go = (size_t)(row0 + r) * K + k0 + c * 8;
            cpa16(stg + so, Am + go);
        }
        #pragma unroll
        for (int i = 0; i < 8; ++i) {            // B: 2048 chunks
            const int lin  = tid + i * 256;      // 0..2047
            const int r    = lin >> 3;           // row 0..255
            const int c    = lin & 7;
            const uint32_t so = (uint32_t)(r * 128 + ((c ^ (r & 7)) << 4));
            const size_t  go = (size_t)(col0 + r) * K + k0 + c * 8;
            cpa16(stg + A_TILE + so, Bm + go);
        }
    };

    fill(0); cpa_commit();

    // lane-constant ldmatrix address components
    const int arow = wm + (lane & 15);               // A row within tile
    const int achi = lane >> 4;                      // A k-chunk hi bit
    const int brow = (lane & 7) + 8 * (lane >> 4);   // B row within 16-col group
    const int bchi = (lane >> 3) & 1;                // B k-chunk hi bit

    for (int ck = 0; ck < NC; ++ck) {
        if (ck + 1 < NC) fill(ck + 1);
        cpa_commit();                   // uniform group count (may be empty)
        cpa_wait1();                    // group for chunk ck complete
        __syncthreads();

        const uint32_t stg = sb + (uint32_t)(ck & 1) * STAGE_BYTES;
        const uint32_t sA = stg;
        const uint32_t sB = stg + A_TILE;

        #pragma unroll
        for (int ks = 0; ks < 4; ++ks) {    // 4 x k16 per 64-chunk
            uint32_t fa[4][4], fb[8][2];
            #pragma unroll
            for (int mt = 0; mt < 4; ++mt) {
                const int r = arow + mt * 16;
                const int c = ks * 2 + achi;
                const uint32_t off = (uint32_t)(r * 128 + ((c ^ (r & 7)) << 4));
                ldsm4(fa[mt][0], fa[mt][1], fa[mt][2], fa[mt][3], sA + off);
            }
            #pragma unroll
            for (int nb2 = 0; nb2 < 4; ++nb2) {   // 16 N-cols per ldsm.x4
                const int r = wn + nb2 * 16 + brow;
                const int c = ks * 2 + bchi;
                const uint32_t off = (uint32_t)(r * 128 + ((c ^ (r & 7)) << 4));
                ldsm4(fb[nb2 * 2][0], fb[nb2 * 2][1],
                      fb[nb2 * 2 + 1][0], fb[nb2 * 2 + 1][1], sB + off);
            }
            #pragma unroll
            for (int mt = 0; mt < 4; ++mt)
                #pragma unroll
                for (int nb = 0; nb < 8; ++nb)
                    mma_f16(acc[mt][nb], fa[mt], fb[nb]);
        }
        __syncthreads();                // stage free before next fill
    }

    // ---- epilogue: direct fp32 stores (frag: rows g,g+8; cols 2i,2i+1)
    const int g  = lane >> 2;
    const int i2 = (lane & 3) * 2;
    #pragma unroll
    for (int mt = 0; mt < 4; ++mt) {
        #pragma unroll
        for (int nb = 0; nb < 8; ++nb) {
            const int row = row0 + wm + mt * 16 + g;
            const int col = col0 + wn + nb * 8 + i2;
            float* p  = C + (size_t)row * Nld + col;
            float* p2 = C + (size_t)(row + 8) * Nld + col;
            *(float2*)p  = make_float2(acc[mt][nb][0], acc[mt][nb][1]);
            *(float2*)p2 = make_float2(acc[mt][nb][2], acc[mt][nb][3]);
        }
    }
}

// ---------------- fp32 -> fp16 convert ---------------------------------------
__global__ void conv_f16(const float* __restrict__ a, __half* __restrict__ o)
{
    const int i = blockIdx.x * blockDim.x + threadIdx.x;
    o[i] = __float2half(a[i]);
}

// ---------------- weight transpose + convert: W[K,N] -> Wt[N][K] fp16 -------
__global__ void __launch_bounds__(256)
wconv_t(const float* __restrict__ W, int K, int N, __half* __restrict__ Wt)
{
    __shared__ float tile[32][33];
    const int n0 = blockIdx.x * 32, k0 = blockIdx.y * 32;
    const int tx = threadIdx.x, ty = threadIdx.y;   // (32, 8)
    #pragma unroll
    for (int r = 0; r < 4; ++r)
        tile[ty + 8 * r][tx] = W[(size_t)(k0 + ty + 8 * r) * N + n0 + tx];
    __syncthreads();
    #pragma unroll
    for (int r = 0; r < 4; ++r) {
        const int n = n0 + ty + 8 * r, k = k0 + tx;
        Wt[(size_t)n * K + k] = __float2half(tile[tx][ty + 8 * r]);
    }
}

// ---------------- SRU recurrence (optionally emits fp16 h) ------------------
__device__ __forceinline__ float sigmoidf_(float x) {
    return 1.0f / (1.0f + expf(-x));
}

template <bool RESID_FROM_U, bool WRITE_F16>
__global__ void __launch_bounds__(HID)
sru_layer_kernel(const float* __restrict__ U, int ustride,
                 const float* __restrict__ resid_h,
                 const float* __restrict__ vc, const float* __restrict__ bias,
                 float* __restrict__ h_out, __half* __restrict__ h16)
{
    const int d = threadIdx.x;
    const int b = blockIdx.x;

    const float vf = vc[d],   vr = vc[HID + d];
    const float bf = bias[d], br = bias[HID + d];

    const float* Ub = U + (size_t)b * T_STEPS * ustride;
    const float* rb = RESID_FROM_U ? nullptr : (resid_h + (size_t)b * T_STEPS * HID);
    const size_t ob = (size_t)b * T_STEPS * HID;

    float c = 0.0f;
    #pragma unroll
    for (int t = 0; t < T_STEPS; ++t) {
        const float* Ut = Ub + (size_t)t * ustride;
        const float u0 = Ut[d];
        const float u1 = Ut[HID + d];
        const float u2 = Ut[2 * HID + d];
        const float xt = RESID_FROM_U ? Ut[3 * HID + d] : rb[(size_t)t * HID + d];

        const float f = sigmoidf_(u1 + vf * c + bf);
        c = f * c + (1.0f - f) * u0;
        const float r = sigmoidf_(u2 + vr * c + br);
        const float h = r * tanhf(c) + (1.0f - r) * xt * SCALE_X;
        const size_t o = ob + (size_t)t * HID + d;
        h_out[o] = h;
        if (WRITE_F16) h16[o] = __float2half(h);
    }
}

// ---- final SRU layer fused with the t-mean: only hbar is materialized ------
__global__ void __launch_bounds__(HID)
sru_layer_mean_kernel(const float* __restrict__ U, int ustride,
                      const float* __restrict__ resid_h,
                      const float* __restrict__ vc, const float* __restrict__ bias,
                      float* __restrict__ hbar)
{
    const int d = threadIdx.x;
    const int b = blockIdx.x;

    const float vf = vc[d],   vr = vc[HID + d];
    const float bf = bias[d], br = bias[HID + d];

    const float* Ub = U + (size_t)b * T_STEPS * ustride;
    const float* rb = resid_h + (size_t)b * T_STEPS * HID;

    float c = 0.0f, s = 0.0f;
    #pragma unroll
    for (int t = 0; t < T_STEPS; ++t) {
        const float* Ut = Ub + (size_t)t * ustride;
        const float u0 = Ut[d];
        const float u1 = Ut[HID + d];
        const float u2 = Ut[2 * HID + d];
        const float xt = rb[(size_t)t * HID + d];

        const float f = sigmoidf_(u1 + vf * c + bf);
        c = f * c + (1.0f - f) * u0;
        const float r = sigmoidf_(u2 + vr * c + br);
        s += r * tanhf(c) + (1.0f - r) * xt * SCALE_X;
    }
    hbar[(size_t)b * HID + d] = s * (1.0f / T_STEPS);
}

// ---------------- FC head ----------------------------------------------------
__global__ void __launch_bounds__(256)
fc_kernel(const float* __restrict__ hbar, const float* __restrict__ w,
          const float* __restrict__ bias, float* __restrict__ out)
{
    __shared__ float hrow[HID];
    __shared__ float part[4][64];
    const int b   = blockIdx.x;
    const int tid = threadIdx.x;

    #pragma unroll
    for (int i = tid; i < HID; i += 256) hrow[i] = hbar[(size_t)b * HID + i];
    __syncthreads();

    const int c  = tid & 63;
    const int sl = tid >> 6;
    float s = 0.0f;
    if (c < NCLS) {
        const int d0 = sl * 256;
        #pragma unroll 8
        for (int d = d0; d < d0 + 256; ++d)
            s = fmaf(hrow[d], w[(size_t)d * NCLS + c], s);
    }
    part[sl][c] = s;
    __syncthreads();

    if (tid < NCLS)
        out[(size_t)b * NCLS + tid] =
            part[0][tid] + part[1][tid] + part[2][tid] + part[3][tid] + bias[tid];
}

// ---------------- launch -----------------------------------------------------
extern "C" void kernel_launch(void* const* d_in, const int* in_sizes, int n_in,
                              void* d_out, int out_size)
{
    const float* x    = (const float*)d_in[0];
    const float* W0   = (const float*)d_in[1];
    const float* W1   = (const float*)d_in[2];
    const float* W2   = (const float*)d_in[3];
    const float* vc0  = (const float*)d_in[4];
    const float* vc1  = (const float*)d_in[5];
    const float* vc2  = (const float*)d_in[6];
    const float* b0   = (const float*)d_in[7];
    const float* b1   = (const float*)d_in[8];
    const float* b2   = (const float*)d_in[9];
    const float* fcw  = (const float*)d_in[10];
    const float* fcb  = (const float*)d_in[11];
    float* out = (float*)d_out;

    float *U, *h0, *h1, *hbar;
    __half *a16, *wt;
    cudaGetSymbolAddress((void**)&U,    g_U);
    cudaGetSymbolAddress((void**)&h0,   g_h0);
    cudaGetSymbolAddress((void**)&h1,   g_h1);
    cudaGetSymbolAddress((void**)&hbar, g_hbar);
    cudaGetSymbolAddress((void**)&a16,  g_a16);
    cudaGetSymbolAddress((void**)&wt,   g_wt);

    cudaFuncSetAttribute(gemm_f16,
                         cudaFuncAttributeMaxDynamicSharedMemorySize, SMEM_GEMM);

    // Layer 0: U = x @ W0  (M=24576, N=4096, K=512)
    conv_f16<<<(MROWS * IMG) / 256, 256>>>(x, a16);
    wconv_t<<<dim3(4096 / 32, IMG / 32), dim3(32, 8)>>>(W0, IMG, 4096, wt);
    gemm_f16<<<dim3(4096 / 256, MROWS / 128), 256, SMEM_GEMM>>>(
        a16, wt, U, IMG, 4096);
    sru_layer_kernel<true, true><<<B_SZ, HID>>>(U, 4096, nullptr, vc0, b0, h0, a16);

    // Layer 1: U = h0 @ W1 (N=3072, K=1024)
    wconv_t<<<dim3(3072 / 32, HID / 32), dim3(32, 8)>>>(W1, HID, 3072, wt);
    gemm_f16<<<dim3(3072 / 256, MROWS / 128), 256, SMEM_GEMM>>>(
        a16, wt, U, HID, 3072);
    sru_layer_kernel<false, true><<<B_SZ, HID>>>(U, 3072, h0, vc1, b1, h1, a16);

    // Layer 2: U = h1 @ W2; fused recurrence + t-mean (h never materialized)
    wconv_t<<<dim3(3072 / 32, HID / 32), dim3(32, 8)>>>(W2, HID, 3072, wt);
    gemm_f16<<<dim3(3072 / 256, MROWS / 128), 256, SMEM_GEMM>>>(
        a16, wt, U, HID, 3072);
    sru_layer_mean_kernel<<<B_SZ, HID>>>(U, 3072, h1, vc2, b2, hbar);

    // FC head on time-averaged h (mean commutes with the linear head)
    fc_kernel<<<B_SZ, 256>>>(hbar, fcw, fcb, out);
}

// round 17
// speedup vs baseline: 5.8485x; 1.0343x over previous
#include <cuda_runtime.h>
#include <cuda_fp16.h>
#include <math.h>
#include <stdint.h>

#define T_STEPS 12
#define HID     1024
#define B_SZ    2048
#define IMG     512
#define NCLS    51
#define MROWS   (T_STEPS * B_SZ)   /* 24576; row r = b*T + t */

#define SCALE_X 1.7320508075688772f  /* sqrt(3) */

// ---------------- scratch (device globals; no allocations allowed) ----------
__device__ __align__(256) __half g_U [(size_t)MROWS * 4096];   // GEMM out (fp16)
__device__ __align__(256) float  g_hbar[(size_t)B_SZ * HID];
// fp16 activation ping-pong buffers (x16 / h per layer)
__device__ __align__(256) __half g_a16[(size_t)MROWS * HID];
__device__ __align__(256) __half g_b16[(size_t)MROWS * HID];
// fp16 transposed weights [N][K] (max 4096x1024)
__device__ __align__(256) __half g_wt[(size_t)4096 * 1024];

// ======================= arch-neutral PTX helpers ===========================
__device__ __forceinline__ uint32_t smem_u32(const void* p) {
    uint32_t a;
    asm("{ .reg .u64 t; cvta.to.shared.u64 t, %1; cvt.u32.u64 %0, t; }"
        : "=r"(a) : "l"(p));
    return a;
}
__device__ __forceinline__ void cpa16(uint32_t dst, const void* src) {
    asm volatile("cp.async.cg.shared.global [%0], [%1], 16;"
                 :: "r"(dst), "l"(src) : "memory");
}
__device__ __forceinline__ void cpa_commit() {
    asm volatile("cp.async.commit_group;" ::: "memory");
}
__device__ __forceinline__ void cpa_wait1() {
    asm volatile("cp.async.wait_group 1;" ::: "memory");
}
__device__ __forceinline__ void ldsm4(uint32_t& r0, uint32_t& r1,
                                      uint32_t& r2, uint32_t& r3, uint32_t addr) {
    asm volatile("ldmatrix.sync.aligned.m8n8.x4.shared.b16 {%0,%1,%2,%3}, [%4];"
                 : "=r"(r0), "=r"(r1), "=r"(r2), "=r"(r3) : "r"(addr));
}
__device__ __forceinline__ void mma_f16(float* c, const uint32_t* a,
                                        const uint32_t* b) {
    asm volatile(
        "mma.sync.aligned.m16n8k16.row.col.f32.f16.f16.f32 "
        "{%0,%1,%2,%3}, {%4,%5,%6,%7}, {%8,%9}, {%0,%1,%2,%3};"
        : "+f"(c[0]), "+f"(c[1]), "+f"(c[2]), "+f"(c[3])
        : "r"(a[0]), "r"(a[1]), "r"(a[2]), "r"(a[3]), "r"(b[0]), "r"(b[1]));
}

// ======================= fp16 tensor-core GEMM ==============================
// C16[M,N] (fp16) = A * B, fp16 operands, fp32 accumulate, fp16 store.
// A: [M,K] row-major; B: [N,K] row-major (pre-transposed -> mma row.col).
// CTA tile 128x256, BK=64 (128B rows, XOR swizzle), 8 warps of 64x64,
// 2-stage cp.async pipeline. grid = (N/256, M/128), 256 threads.
#define A_TILE      16384                   /* 128 rows x 128 B */
#define B_TILE      32768                   /* 256 rows x 128 B */
#define STAGE_BYTES (A_TILE + B_TILE)       /* 48 KB */
#define SMEM_GEMM   (2 * STAGE_BYTES)       /* 96 KB */

__global__ void __launch_bounds__(256)
gemm_f16(const __half* __restrict__ Am, const __half* __restrict__ Bm,
         __half* __restrict__ C, int K, int Nld)
{
    extern __shared__ char smem[];
    const uint32_t sb = smem_u32(smem);
    const int tid  = threadIdx.x;
    const int lane = tid & 31;
    const int wid  = tid >> 5;
    const int row0 = blockIdx.y * 128;
    const int col0 = blockIdx.x * 256;
    const int wm   = (wid >> 2) * 64;   // warp M offset (0 / 64)
    const int wn   = (wid & 3) * 64;    // warp N offset (0..192)

    const int NC = K >> 6;              // K/64 chunks

    float acc[4][8][4];
    #pragma unroll
    for (int i = 0; i < 4; ++i)
        #pragma unroll
        for (int j = 0; j < 8; ++j)
            #pragma unroll
            for (int q = 0; q < 4; ++q) acc[i][j][q] = 0.0f;

    // ---- stage fill: A (128x8) + B (256x8) 16B chunks; 12 cp.async/thread
    auto fill = [&](int ck) {
        const int k0 = ck << 6;
        const uint32_t stg = sb + (uint32_t)(ck & 1) * STAGE_BYTES;
        #pragma unroll
        for (int i = 0; i < 4; ++i) {            // A: 1024 chunks
            const int lin  = tid + i * 256;      // 0..1023
            const int r    = lin >> 3;
            const int c    = lin & 7;
            const uint32_t so = (uint32_t)(r * 128 + ((c ^ (r & 7)) << 4));
            const size_t  go = (size_t)(row0 + r) * K + k0 + c * 8;
            cpa16(stg + so, Am + go);
        }
        #pragma unroll
        for (int i = 0; i < 8; ++i) {            // B: 2048 chunks
            const int lin  = tid + i * 256;      // 0..2047
            const int r    = lin >> 3;           // row 0..255
            const int c    = lin & 7;
            const uint32_t so = (uint32_t)(r * 128 + ((c ^ (r & 7)) << 4));
            const size_t  go = (size_t)(col0 + r) * K + k0 + c * 8;
            cpa16(stg + A_TILE + so, Bm + go);
        }
    };

    fill(0); cpa_commit();

    // lane-constant ldmatrix address components
    const int arow = wm + (lane & 15);               // A row within tile
    const int achi = lane >> 4;                      // A k-chunk hi bit
    const int brow = (lane & 7) + 8 * (lane >> 4);   // B row within 16-col group
    const int bchi = (lane >> 3) & 1;                // B k-chunk hi bit

    for (int ck = 0; ck < NC; ++ck) {
        if (ck + 1 < NC) fill(ck + 1);
        cpa_commit();                   // uniform group count (may be empty)
        cpa_wait1();                    // group for chunk ck complete
        __syncthreads();

        const uint32_t stg = sb + (uint32_t)(ck & 1) * STAGE_BYTES;
        const uint32_t sA = stg;
        const uint32_t sB = stg + A_TILE;

        #pragma unroll
        for (int ks = 0; ks < 4; ++ks) {    // 4 x k16 per 64-chunk
            uint32_t fa[4][4], fb[8][2];
            #pragma unroll
            for (int mt = 0; mt < 4; ++mt) {
                const int r = arow + mt * 16;
                const int c = ks * 2 + achi;
                const uint32_t off = (uint32_t)(r * 128 + ((c ^ (r & 7)) << 4));
                ldsm4(fa[mt][0], fa[mt][1], fa[mt][2], fa[mt][3], sA + off);
            }
            #pragma unroll
            for (int nb2 = 0; nb2 < 4; ++nb2) {   // 16 N-cols per ldsm.x4
                const int r = wn + nb2 * 16 + brow;
                const int c = ks * 2 + bchi;
                const uint32_t off = (uint32_t)(r * 128 + ((c ^ (r & 7)) << 4));
                ldsm4(fb[nb2 * 2][0], fb[nb2 * 2][1],
                      fb[nb2 * 2 + 1][0], fb[nb2 * 2 + 1][1], sB + off);
            }
            #pragma unroll
            for (int mt = 0; mt < 4; ++mt)
                #pragma unroll
                for (int nb = 0; nb < 8; ++nb)
                    mma_f16(acc[mt][nb], fa[mt], fb[nb]);
        }
        __syncthreads();                // stage free before next fill
    }

    // ---- epilogue: fp16 stores (frag: rows g,g+8; cols 2i,2i+1 -> __half2)
    const int g  = lane >> 2;
    const int i2 = (lane & 3) * 2;
    #pragma unroll
    for (int mt = 0; mt < 4; ++mt) {
        #pragma unroll
        for (int nb = 0; nb < 8; ++nb) {
            const int row = row0 + wm + mt * 16 + g;
            const int col = col0 + wn + nb * 8 + i2;
            __half* p  = C + (size_t)row * Nld + col;
            __half* p2 = C + (size_t)(row + 8) * Nld + col;
            *(__half2*)p  = __floats2half2_rn(acc[mt][nb][0], acc[mt][nb][1]);
            *(__half2*)p2 = __floats2half2_rn(acc[mt][nb][2], acc[mt][nb][3]);
        }
    }
}

// ---------------- fp32 -> fp16 convert ---------------------------------------
__global__ void conv_f16(const float* __restrict__ a, __half* __restrict__ o)
{
    const int i = blockIdx.x * blockDim.x + threadIdx.x;
    o[i] = __float2half(a[i]);
}

// ---------------- weight transpose + convert: W[K,N] -> Wt[N][K] fp16 -------
__global__ void __launch_bounds__(256)
wconv_t(const float* __restrict__ W, int K, int N, __half* __restrict__ Wt)
{
    __shared__ float tile[32][33];
    const int n0 = blockIdx.x * 32, k0 = blockIdx.y * 32;
    const int tx = threadIdx.x, ty = threadIdx.y;   // (32, 8)
    #pragma unroll
    for (int r = 0; r < 4; ++r)
        tile[ty + 8 * r][tx] = W[(size_t)(k0 + ty + 8 * r) * N + n0 + tx];
    __syncthreads();
    #pragma unroll
    for (int r = 0; r < 4; ++r) {
        const int n = n0 + ty + 8 * r, k = k0 + tx;
        Wt[(size_t)n * K + k] = __float2half(tile[tx][ty + 8 * r]);
    }
}

// ---------------- SRU recurrence (all-fp16 I/O, fp32 math) ------------------
__device__ __forceinline__ float sigmoidf_(float x) {
    return 1.0f / (1.0f + expf(-x));
}

template <bool RESID_FROM_U>
__global__ void __launch_bounds__(HID)
sru16_kernel(const __half* __restrict__ U, int ustride,
             const __half* __restrict__ resid,
             const float* __restrict__ vc, const float* __restrict__ bias,
             __half* __restrict__ h_out)
{
    const int d = threadIdx.x;
    const int b = blockIdx.x;

    const float vf = vc[d],   vr = vc[HID + d];
    const float bf = bias[d], br = bias[HID + d];

    const __half* Ub = U + (size_t)b * T_STEPS * ustride;
    const __half* rb = RESID_FROM_U ? nullptr : (resid + (size_t)b * T_STEPS * HID);
    __half* hb = h_out + (size_t)b * T_STEPS * HID;

    float c = 0.0f;
    #pragma unroll
    for (int t = 0; t < T_STEPS; ++t) {
        const __half* Ut = Ub + (size_t)t * ustride;
        const float u0 = __half2float(Ut[d]);
        const float u1 = __half2float(Ut[HID + d]);
        const float u2 = __half2float(Ut[2 * HID + d]);
        const float xt = RESID_FROM_U ? __half2float(Ut[3 * HID + d])
                                      : __half2float(rb[(size_t)t * HID + d]);

        const float f = sigmoidf_(u1 + vf * c + bf);
        c = f * c + (1.0f - f) * u0;
        const float r = sigmoidf_(u2 + vr * c + br);
        hb[(size_t)t * HID + d] =
            __float2half(r * tanhf(c) + (1.0f - r) * xt * SCALE_X);
    }
}

// ---- final SRU layer fused with the t-mean: only hbar (fp32) materialized --
__global__ void __launch_bounds__(HID)
sru16_mean_kernel(const __half* __restrict__ U, int ustride,
                  const __half* __restrict__ resid,
                  const float* __restrict__ vc, const float* __restrict__ bias,
                  float* __restrict__ hbar)
{
    const int d = threadIdx.x;
    const int b = blockIdx.x;

    const float vf = vc[d],   vr = vc[HID + d];
    const float bf = bias[d], br = bias[HID + d];

    const __half* Ub = U + (size_t)b * T_STEPS * ustride;
    const __half* rb = resid + (size_t)b * T_STEPS * HID;

    float c = 0.0f, s = 0.0f;
    #pragma unroll
    for (int t = 0; t < T_STEPS; ++t) {
        const __half* Ut = Ub + (size_t)t * ustride;
        const float u0 = __half2float(Ut[d]);
        const float u1 = __half2float(Ut[HID + d]);
        const float u2 = __half2float(Ut[2 * HID + d]);
        const float xt = __half2float(rb[(size_t)t * HID + d]);

        const float f = sigmoidf_(u1 + vf * c + bf);
        c = f * c + (1.0f - f) * u0;
        const float r = sigmoidf_(u2 + vr * c + br);
        s += r * tanhf(c) + (1.0f - r) * xt * SCALE_X;
    }
    hbar[(size_t)b * HID + d] = s * (1.0f / T_STEPS);
}

// ---------------- FC head ----------------------------------------------------
__global__ void __launch_bounds__(256)
fc_kernel(const float* __restrict__ hbar, const float* __restrict__ w,
          const float* __restrict__ bias, float* __restrict__ out)
{
    __shared__ float hrow[HID];
    __shared__ float part[4][64];
    const int b   = blockIdx.x;
    const int tid = threadIdx.x;

    #pragma unroll
    for (int i = tid; i < HID; i += 256) hrow[i] = hbar[(size_t)b * HID + i];
    __syncthreads();

    const int c  = tid & 63;
    const int sl = tid >> 6;
    float s = 0.0f;
    if (c < NCLS) {
        const int d0 = sl * 256;
        #pragma unroll 8
        for (int d = d0; d < d0 + 256; ++d)
            s = fmaf(hrow[d], w[(size_t)d * NCLS + c], s);
    }
    part[sl][c] = s;
    __syncthreads();

    if (tid < NCLS)
        out[(size_t)b * NCLS + tid] =
            part[0][tid] + part[1][tid] + part[2][tid] + part[3][tid] + bias[tid];
}

// ---------------- launch -----------------------------------------------------
extern "C" void kernel_launch(void* const* d_in, const int* in_sizes, int n_in,
                              void* d_out, int out_size)
{
    const float* x    = (const float*)d_in[0];
    const float* W0   = (const float*)d_in[1];
    const float* W1   = (const float*)d_in[2];
    const float* W2   = (const float*)d_in[3];
    const float* vc0  = (const float*)d_in[4];
    const float* vc1  = (const float*)d_in[5];
    const float* vc2  = (const float*)d_in[6];
    const float* b0   = (const float*)d_in[7];
    const float* b1   = (const float*)d_in[8];
    const float* b2   = (const float*)d_in[9];
    const float* fcw  = (const float*)d_in[10];
    const float* fcb  = (const float*)d_in[11];
    float* out = (float*)d_out;

    float *hbar;
    __half *U, *a16, *b16, *wt;
    cudaGetSymbolAddress((void**)&U,    g_U);
    cudaGetSymbolAddress((void**)&hbar, g_hbar);
    cudaGetSymbolAddress((void**)&a16,  g_a16);
    cudaGetSymbolAddress((void**)&b16,  g_b16);
    cudaGetSymbolAddress((void**)&wt,   g_wt);

    cudaFuncSetAttribute(gemm_f16,
                         cudaFuncAttributeMaxDynamicSharedMemorySize, SMEM_GEMM);

    // Layer 0: U = x @ W0  (M=24576, N=4096, K=512); h0 -> b16
    conv_f16<<<(MROWS * IMG) / 256, 256>>>(x, a16);
    wconv_t<<<dim3(4096 / 32, IMG / 32), dim3(32, 8)>>>(W0, IMG, 4096, wt);
    gemm_f16<<<dim3(4096 / 256, MROWS / 128), 256, SMEM_GEMM>>>(
        a16, wt, U, IMG, 4096);
    sru16_kernel<true><<<B_SZ, HID>>>(U, 4096, nullptr, vc0, b0, b16);

    // Layer 1: U = h0 @ W1 (N=3072, K=1024); h1 -> a16 (x16 dead after gemm0)
    wconv_t<<<dim3(3072 / 32, HID / 32), dim3(32, 8)>>>(W1, HID, 3072, wt);
    gemm_f16<<<dim3(3072 / 256, MROWS / 128), 256, SMEM_GEMM>>>(
        b16, wt, U, HID, 3072);
    sru16_kernel<false><<<B_SZ, HID>>>(U, 3072, b16, vc1, b1, a16);

    // Layer 2: U = h1 @ W2; fused recurrence + t-mean (h2 never materialized)
    wconv_t<<<dim3(3072 / 32, HID / 32), dim3(32, 8)>>>(W2, HID, 3072, wt);
    gemm_f16<<<dim3(3072 / 256, MROWS / 128), 256, SMEM_GEMM>>>(
        a16, wt, U, HID, 3072);
    sru16_mean_kernel<<<B_SZ, HID>>>(U, 3072, a16, vc2, b2, hbar);

    // FC head on time-averaged h (mean commutes with the linear head)
    fc_kernel<<<B_SZ, 256>>>(hbar, fcw, fcb, out);
}